// round 9
// baseline (speedup 1.0000x reference)
#include <cuda_runtime.h>
#include <cstdint>

#define BATCH 8
#define L 512
#define D 512
#define OUTR 1536
#define OUTC 2560
#define NCHUNK 16
#define LDA 40     // [row][k] smem stride (floats)
#define LDBPV 136  // [k][n] smem stride for PV B (floats)

// Stage sizes (floats)
#define STAGE_S  (2 * 128 * LDA)              // 10240
#define STAGE_PV (128 * LDA + 32 * LDBPV)     // 9472
#define SMEM_S   (2 * STAGE_S * 4)            // 81920 B (2-stage)
#define SMEM_PV  (2 * STAGE_PV * 4)           // 75776 B (2-stage)

// Scratch (static device memory; allocation-free per harness rules)
__device__ float g_S[3][BATCH * L * L];     // S natural; P stored tf32 + k-permuted
__device__ float g_Xw[3][BATCH * L * D];    // tf32(X * wM), k-permuted
__device__ float g_Yc[2][BATCH * L * D];    // tf32(enc_b), tf32(enc_c), natural
__device__ float g_r[3][2][BATCH * L];      // rX, rY per pair
__device__ float g_m[3][BATCH * L];         // row max per pair
__device__ float g_v[3][BATCH * D];         // b2a vector per pair

// ===========================================================================
// helpers
// ===========================================================================
__device__ __forceinline__ uint32_t f2tf(float f) {
    uint32_t r;
    asm("cvt.rna.tf32.f32 %0, %1;" : "=r"(r) : "f"(f));
    return r;
}
__device__ __forceinline__ float4 cvt4(float4 v) {
    v.x = __uint_as_float(f2tf(v.x));
    v.y = __uint_as_float(f2tf(v.y));
    v.z = __uint_as_float(f2tf(v.z));
    v.w = __uint_as_float(f2tf(v.w));
    return v;
}
// Within-8-group k permutation: positions [0..7] hold cols [0,4,1,5,2,6,3,7].
__device__ __forceinline__ float4 perm8(float4 v) {
    float4 q;
    q.x = __shfl_xor_sync(0xFFFFFFFFu, v.x, 1);
    q.y = __shfl_xor_sync(0xFFFFFFFFu, v.y, 1);
    q.z = __shfl_xor_sync(0xFFFFFFFFu, v.z, 1);
    q.w = __shfl_xor_sync(0xFFFFFFFFu, v.w, 1);
    return (threadIdx.x & 1) ? make_float4(q.z, v.z, q.w, v.w)
                             : make_float4(v.x, q.x, v.y, q.y);
}
__device__ __forceinline__ void mma8(float* c, const uint32_t* a, const uint32_t* b) {
    asm volatile(
        "mma.sync.aligned.m16n8k8.row.col.f32.tf32.tf32.f32 "
        "{%0,%1,%2,%3}, {%4,%5,%6,%7}, {%8,%9}, {%0,%1,%2,%3};"
        : "+f"(c[0]), "+f"(c[1]), "+f"(c[2]), "+f"(c[3])
        : "r"(a[0]), "r"(a[1]), "r"(a[2]), "r"(a[3]), "r"(b[0]), "r"(b[1]));
}
__device__ __forceinline__ void cp16(float* dst, const float* src) {
    uint32_t d = (uint32_t)__cvta_generic_to_shared(dst);
    asm volatile("cp.async.cg.shared.global [%0], [%1], 16;" :: "r"(d), "l"(src) : "memory");
}
__device__ __forceinline__ void cp_commit() {
    asm volatile("cp.async.commit_group;" ::: "memory");
}

// ===========================================================================
// prep: per encoder matrix: 2 row-dots + tf32 operand copies (unchanged R8)
// ===========================================================================
__global__ void prep_kernel(const float* __restrict__ ea, const float* __restrict__ eb,
                            const float* __restrict__ ec,
                            const float* __restrict__ wab, const float* __restrict__ wac,
                            const float* __restrict__ wbc) {
    int mat = blockIdx.y;
    int row = blockIdx.x * 8 + (threadIdx.x >> 5);
    int lane = threadIdx.x & 31;

    const float *src, *w1, *w2, *sc1, *sc2;
    float *r1, *r2, *d1, *d2;
    int p1, p2;
    if (mat == 0) {
        src = ea; w1 = wab; r1 = &g_r[0][0][0]; w2 = wac; r2 = &g_r[1][0][0];
        sc1 = wab + 1024; d1 = g_Xw[0]; p1 = 1;
        sc2 = wac + 1024; d2 = g_Xw[1]; p2 = 1;
    } else if (mat == 1) {
        src = eb; w1 = wab + 512; r1 = &g_r[0][1][0]; w2 = wbc; r2 = &g_r[2][0][0];
        sc1 = wbc + 1024; d1 = g_Xw[2]; p1 = 1;
        sc2 = nullptr; d2 = g_Yc[0]; p2 = 0;
    } else {
        src = ec; w1 = wac + 512; r1 = &g_r[1][1][0]; w2 = wbc + 512; r2 = &g_r[2][1][0];
        sc1 = nullptr; d1 = g_Yc[1]; p1 = 0;
        sc2 = nullptr; d2 = nullptr; p2 = 0;
    }

    const float* rp = src + (size_t)row * D;
    float4 x[4];
    float s1 = 0.f, s2 = 0.f;
#pragma unroll
    for (int t = 0; t < 4; t++) {
        int k = (t * 32 + lane) * 4;
        x[t] = *(const float4*)(rp + k);
        float4 a = *(const float4*)(w1 + k);
        s1 += x[t].x * a.x + x[t].y * a.y + x[t].z * a.z + x[t].w * a.w;
        float4 b = *(const float4*)(w2 + k);
        s2 += x[t].x * b.x + x[t].y * b.y + x[t].z * b.z + x[t].w * b.w;
    }
#pragma unroll
    for (int o = 16; o; o >>= 1) {
        s1 += __shfl_xor_sync(0xFFFFFFFFu, s1, o);
        s2 += __shfl_xor_sync(0xFFFFFFFFu, s2, o);
    }
    if (!lane) { r1[row] = s1; r2[row] = s2; }

#pragma unroll
    for (int t = 0; t < 4; t++) {
        int k = (t * 32 + lane) * 4;
        float4 v = x[t];
        if (sc1) {
            float4 s = *(const float4*)(sc1 + k);
            v.x *= s.x; v.y *= s.y; v.z *= s.z; v.w *= s.w;
        }
        v = cvt4(v);
        if (p1) v = perm8(v);
        *(float4*)(d1 + (size_t)row * D + k) = v;
    }
    if (d2) {
#pragma unroll
        for (int t = 0; t < 4; t++) {
            int k = (t * 32 + lane) * 4;
            float4 v = x[t];
            if (sc2) {
                float4 s = *(const float4*)(sc2 + k);
                v.x *= s.x; v.y *= s.y; v.z *= s.z; v.w *= s.w;
            }
            v = cvt4(v);
            if (p2) v = perm8(v);
            *(float4*)(d2 + (size_t)row * D + k) = v;
        }
    }
}

// ===========================================================================
// S GEMM (batched): S = rX + rY + Xw @ Yc^T.  grid (4,4,24), 128 threads,
// 4 warps in 2x2 grid, warp tile 64x64. A frags float2 (k-perm); B scalar.
// ===========================================================================
__global__ __launch_bounds__(128, 2)
void gemm_s_mma(const float* __restrict__ dummy) {
    extern __shared__ float sm[];
    int pair = blockIdx.z >> 3, b = blockIdx.z & 7;
    int yt = (pair == 0) ? 0 : 1;
    int i0 = blockIdx.y * 128, j0 = blockIdx.x * 128;
    const float* Ag = g_Xw[pair] + ((size_t)b * L + i0) * D;
    const float* Bg = g_Yc[yt] + ((size_t)b * L + j0) * D;
    int tid = threadIdx.x;

    int lane = tid & 31, w = tid >> 5;          // 4 warps
    int ar = lane >> 2, ac = lane & 3;
    int mbase = (w & 1) * 64, nbase = (w >> 1) * 64;
    float acc[4][8][4] = {};

    auto issue = [&](int c, int st) {
        float* As = sm + st * STAGE_S;
        float* Bs = As + 128 * LDA;
        int k0 = c * 32;
#pragma unroll
        for (int it = 0; it < 8; it++) {
            int i = it * 128 + tid;
            int row = i >> 3, c4 = (i & 7) << 2;
            cp16(As + row * LDA + c4, Ag + (size_t)row * D + k0 + c4);
            cp16(Bs + row * LDA + c4, Bg + (size_t)row * D + k0 + c4);
        }
        cp_commit();
    };

    issue(0, 0);
    for (int c = 0; c < NCHUNK; c++) {
        if (c + 1 < NCHUNK) {
            issue(c + 1, (c + 1) & 1);
            asm volatile("cp.async.wait_group 1;" ::: "memory");
        } else {
            asm volatile("cp.async.wait_group 0;" ::: "memory");
        }
        __syncthreads();
        const float* a_s = sm + (c & 1) * STAGE_S;
        const float* b_s = a_s + 128 * LDA;
#pragma unroll
        for (int ks = 0; ks < 4; ks++) {
            uint32_t af[4][4], bf[8][2];
#pragma unroll
            for (int mt = 0; mt < 4; mt++) {
                const float* p = a_s + (mbase + mt * 16 + ar) * LDA + ks * 8 + ac * 2;
                float2 a0 = *(const float2*)p;
                float2 a1 = *(const float2*)(p + 8 * LDA);
                af[mt][0] = __float_as_uint(a0.x);
                af[mt][1] = __float_as_uint(a1.x);
                af[mt][2] = __float_as_uint(a0.y);
                af[mt][3] = __float_as_uint(a1.y);
            }
#pragma unroll
            for (int nt = 0; nt < 8; nt++) {
                const float* q = b_s + (nbase + nt * 8 + ar) * LDA + ks * 8 + ac;
                bf[nt][0] = __float_as_uint(q[0]);
                bf[nt][1] = __float_as_uint(q[4]);
            }
#pragma unroll
            for (int mt = 0; mt < 4; mt++)
#pragma unroll
                for (int nt = 0; nt < 8; nt++) mma8(acc[mt][nt], af[mt], bf[nt]);
        }
        __syncthreads();
    }

    const float* rx = g_r[pair][0] + b * L + i0;
    const float* ry = g_r[pair][1] + b * L + j0;
    float* Sp = g_S[pair] + ((size_t)b * L + i0) * L + j0;
#pragma unroll
    for (int mt = 0; mt < 4; mt++) {
        int r = mbase + mt * 16 + ar;
        float rx0 = rx[r], rx1 = rx[r + 8];
#pragma unroll
        for (int nt = 0; nt < 8; nt++) {
            int cI = nbase + nt * 8 + ac * 2;
            float ry0 = ry[cI], ry1 = ry[cI + 1];
            float2 v0 = make_float2(acc[mt][nt][0] + rx0 + ry0, acc[mt][nt][1] + rx0 + ry1);
            float2 v1 = make_float2(acc[mt][nt][2] + rx1 + ry0, acc[mt][nt][3] + rx1 + ry1);
            *(float2*)(Sp + (size_t)r * L + cI) = v0;
            *(float2*)(Sp + (size_t)(r + 8) * L + cI) = v1;
        }
    }
}

// ===========================================================================
// PV GEMM (batched): O = P @ Yc; fused concat writes.  grid (4,4,24),
// 128 threads, warp tile 64x64. A frags float2 (j-perm P); B scalar [k][n].
// ===========================================================================
__constant__ int c_secRowA[3] = {0, 0, 512};
__constant__ int c_offRawA[3] = {512, 1024, 1024};
__constant__ int c_offProdA[3] = {1536, 2048, 2048};

__global__ __launch_bounds__(128, 2)
void gemm_pv_mma(const float* __restrict__ ea, const float* __restrict__ eb,
                 const float* __restrict__ ec, float* __restrict__ out) {
    extern __shared__ float sm[];
    int pair = blockIdx.z >> 3, b = blockIdx.z & 7;
    int yt = (pair == 0) ? 0 : 1;
    const float* E = (pair == 2) ? eb : ea;
    int secRow = c_secRowA[pair], offRaw = c_offRawA[pair], offProd = c_offProdA[pair];
    int i0 = blockIdx.y * 128, d0 = blockIdx.x * 128;
    const float* Ag = g_S[pair] + ((size_t)b * L + i0) * L;
    const float* Bg = g_Yc[yt] + (size_t)b * L * D + d0;
    int tid = threadIdx.x;

    int lane = tid & 31, w = tid >> 5;
    int ar = lane >> 2, ac = lane & 3;
    int mbase = (w & 1) * 64, nbase = (w >> 1) * 64;
    float acc[4][8][4] = {};

    auto issue = [&](int c, int st) {
        float* As = sm + st * STAGE_PV;
        float* Bs = As + 128 * LDA;
        int k0 = c * 32;
#pragma unroll
        for (int it = 0; it < 8; it++) {
            int i = it * 128 + tid;
            int arow = i >> 3, ac4 = (i & 7) << 2;
            cp16(As + arow * LDA + ac4, Ag + (size_t)arow * L + k0 + ac4);
            int brow = i >> 5, bc4 = (i & 31) << 2;
            cp16(Bs + brow * LDBPV + bc4, Bg + (size_t)(k0 + brow) * D + bc4);
        }
        cp_commit();
    };

    issue(0, 0);
    for (int c = 0; c < NCHUNK; c++) {
        if (c + 1 < NCHUNK) {
            issue(c + 1, (c + 1) & 1);
            asm volatile("cp.async.wait_group 1;" ::: "memory");
        } else {
            asm volatile("cp.async.wait_group 0;" ::: "memory");
        }
        __syncthreads();
        const float* a_s = sm + (c & 1) * STAGE_PV;
        const float* b_s = a_s + 128 * LDA;
#pragma unroll
        for (int ks = 0; ks < 4; ks++) {
            uint32_t af[4][4], bf[8][2];
#pragma unroll
            for (int mt = 0; mt < 4; mt++) {
                const float* p = a_s + (mbase + mt * 16 + ar) * LDA + ks * 8 + ac * 2;
                float2 a0 = *(const float2*)p;
                float2 a1 = *(const float2*)(p + 8 * LDA);
                af[mt][0] = __float_as_uint(a0.x);
                af[mt][1] = __float_as_uint(a1.x);
                af[mt][2] = __float_as_uint(a0.y);
                af[mt][3] = __float_as_uint(a1.y);
            }
#pragma unroll
            for (int nt = 0; nt < 8; nt++) {
                const float* q = b_s + (ks * 8 + ac) * LDBPV + nbase + nt * 8 + ar;
                bf[nt][0] = __float_as_uint(q[0]);
                bf[nt][1] = __float_as_uint(q[4 * LDBPV]);
            }
#pragma unroll
            for (int mt = 0; mt < 4; mt++)
#pragma unroll
                for (int nt = 0; nt < 8; nt++) mma8(acc[mt][nt], af[mt], bf[nt]);
        }
        __syncthreads();
    }

#pragma unroll
    for (int mt = 0; mt < 4; mt++) {
        int r = mbase + mt * 16 + ar;
        int i = i0 + r;
        const float* e0p = E + ((size_t)b * L + i) * D + d0;
        float* o0p = out + ((size_t)b * OUTR + secRow + i) * OUTC;
#pragma unroll
        for (int nt = 0; nt < 8; nt++) {
            int cI = nbase + nt * 8 + ac * 2;
            float2 e0 = *(const float2*)(e0p + cI);
            float2 e1 = *(const float2*)(e0p + 8 * D + cI);
            float2 v0 = make_float2(acc[mt][nt][0], acc[mt][nt][1]);
            float2 v1 = make_float2(acc[mt][nt][2], acc[mt][nt][3]);
            *(float2*)(o0p + offRaw + d0 + cI) = v0;
            *(float2*)(o0p + 8 * OUTC + offRaw + d0 + cI) = v1;
            *(float2*)(o0p + offProd + d0 + cI) = make_float2(v0.x * e0.x, v0.y * e0.y);
            *(float2*)(o0p + 8 * OUTC + offProd + d0 + cI) = make_float2(v1.x * e1.x, v1.y * e1.y);
        }
    }
}

// ===========================================================================
// softmax (batched): in-place row softmax; P stored tf32 + k-permuted. grid (512,3)
// ===========================================================================
__global__ void softmax_kernel(const float* __restrict__ dummy) {
    int pair = blockIdx.y;
    int row = blockIdx.x * 8 + (threadIdx.x >> 5);
    int lane = threadIdx.x & 31;
    float* r = g_S[pair] + (size_t)row * L;
    float4 v[4];
    float mx = -1e30f;
#pragma unroll
    for (int t = 0; t < 4; t++) {
        v[t] = ((float4*)r)[t * 32 + lane];
        mx = fmaxf(mx, fmaxf(fmaxf(v[t].x, v[t].y), fmaxf(v[t].z, v[t].w)));
    }
#pragma unroll
    for (int o = 16; o; o >>= 1) mx = fmaxf(mx, __shfl_xor_sync(0xFFFFFFFFu, mx, o));
    float s = 0.f;
#pragma unroll
    for (int t = 0; t < 4; t++) {
        v[t].x = __expf(v[t].x - mx);
        v[t].y = __expf(v[t].y - mx);
        v[t].z = __expf(v[t].z - mx);
        v[t].w = __expf(v[t].w - mx);
        s += v[t].x + v[t].y + v[t].z + v[t].w;
    }
#pragma unroll
    for (int o = 16; o; o >>= 1) s += __shfl_xor_sync(0xFFFFFFFFu, s, o);
    float inv = 1.f / s;
#pragma unroll
    for (int t = 0; t < 4; t++) {
        v[t].x *= inv; v[t].y *= inv; v[t].z *= inv; v[t].w *= inv;
        ((float4*)r)[t * 32 + lane] = perm8(cvt4(v[t]));
    }
    if (!lane) g_m[pair][row] = mx;
}

// ===========================================================================
// beta (batched): beta = softmax_i(m); v = sum_i beta_i * X[b,i,:]. grid (8,3)
// ===========================================================================
__global__ __launch_bounds__(512)
void beta_b2a_kernel(const float* __restrict__ ea, const float* __restrict__ eb,
                     const float* __restrict__ ec) {
    int b = blockIdx.x, pair = blockIdx.y, t = threadIdx.x;
    const float* X = (pair == 2) ? eb : ea;
    int lane = t & 31, wid = t >> 5;
    __shared__ float sb[512];
    __shared__ float redm[16];
    __shared__ float reds[16];
    __shared__ float bc[2];
    float mv = g_m[pair][b * L + t];
    float v = mv;
#pragma unroll
    for (int o = 16; o; o >>= 1) v = fmaxf(v, __shfl_xor_sync(0xFFFFFFFFu, v, o));
    if (!lane) redm[wid] = v;
    __syncthreads();
    if (t == 0) {
        float m2 = redm[0];
        for (int i = 1; i < 16; i++) m2 = fmaxf(m2, redm[i]);
        bc[0] = m2;
    }
    __syncthreads();
    float mx = bc[0];
    float e = __expf(mv - mx);
    v = e;
#pragma unroll
    for (int o = 16; o; o >>= 1) v += __shfl_xor_sync(0xFFFFFFFFu, v, o);
    if (!lane) reds[wid] = v;
    __syncthreads();
    if (t == 0) {
        float s = 0.f;
        for (int i = 0; i < 16; i++) s += reds[i];
        bc[1] = s;
    }
    __syncthreads();
    sb[t] = e / bc[1];
    __syncthreads();
    const float* Xb = X + (size_t)b * L * D;
    float acc = 0.f;
#pragma unroll 8
    for (int i = 0; i < L; i++) acc += sb[i] * Xb[(size_t)i * D + t];
    g_v[pair][b * D + t] = acc;
}

// ===========================================================================
// tail: fused enc copy + vector broadcast (raw + E*vec). grid (512, 8, 3)
// ===========================================================================
__global__ void tail_kernel(const float* __restrict__ ea, const float* __restrict__ eb,
                            const float* __restrict__ ec, float* __restrict__ out) {
    int s = blockIdx.z, b = blockIdx.y, r = blockIdx.x;
    const float* E = (s == 0) ? ea : (s == 1) ? eb : ec;
    int t = threadIdx.x;
    float4 e = ((const float4*)(E + ((size_t)b * L + r) * D))[t];
    float* row = out + ((size_t)b * OUTR + s * 512 + r) * OUTC;
    ((float4*)row)[t] = e;
    if (s == 1) {
        float4 vv = ((const float4*)(&g_v[0][b * D]))[t];
        ((float4*)(row + 512))[t] = vv;
        ((float4*)(row + 1536))[t] = make_float4(vv.x * e.x, vv.y * e.y, vv.z * e.z, vv.w * e.w);
    } else if (s == 2) {
        float4 v1 = ((const float4*)(&g_v[1][b * D]))[t];
        ((float4*)(row + 512))[t] = v1;
        ((float4*)(row + 1536))[t] = make_float4(v1.x * e.x, v1.y * e.y, v1.z * e.z, v1.w * e.w);
        float4 v2 = ((const float4*)(&g_v[2][b * D]))[t];
        ((float4*)(row + 1024))[t] = v2;
        ((float4*)(row + 2048))[t] = make_float4(v2.x * e.x, v2.y * e.y, v2.z * e.z, v2.w * e.w);
    }
}

// ===========================================================================
extern "C" void kernel_launch(void* const* d_in, const int* in_sizes, int n_in,
                              void* d_out, int out_size) {
    const float* ea = (const float*)d_in[0];
    const float* eb = (const float*)d_in[1];
    const float* ec = (const float*)d_in[2];
    const float* wab = (const float*)d_in[3];
    const float* wac = (const float*)d_in[4];
    const float* wbc = (const float*)d_in[5];
    float* out = (float*)d_out;

    cudaFuncSetAttribute(gemm_s_mma, cudaFuncAttributeMaxDynamicSharedMemorySize, SMEM_S);
    cudaFuncSetAttribute(gemm_pv_mma, cudaFuncAttributeMaxDynamicSharedMemorySize, SMEM_PV);

    prep_kernel<<<dim3(512, 3), 256>>>(ea, eb, ec, wab, wac, wbc);
    gemm_s_mma<<<dim3(4, 4, 24), 128, SMEM_S>>>(nullptr);
    softmax_kernel<<<dim3(512, 3), 256>>>(nullptr);
    gemm_pv_mma<<<dim3(4, 4, 24), 128, SMEM_PV>>>(ea, eb, ec, out);
    beta_b2a_kernel<<<dim3(8, 3), 512>>>(ea, eb, ec);
    tail_kernel<<<dim3(512, 8, 3), 128>>>(ea, eb, ec, out);
}

// round 10
// speedup vs baseline: 1.0102x; 1.0102x over previous
#include <cuda_runtime.h>
#include <cstdint>

#define BATCH 8
#define L 512
#define D 512
#define OUTR 1536
#define OUTC 2560
#define NCHUNK 16
#define LDA 40     // [row][k] smem stride (floats)
#define LDBPV 136  // [k][n] smem stride for PV B (floats)

// Stage sizes (floats)
#define STAGE_S  (2 * 128 * LDA)              // 10240
#define STAGE_PV (128 * LDA + 32 * LDBPV)     // 9472
#define SMEM_S   (2 * STAGE_S * 4)            // 81920 B (2-stage)
#define SMEM_PV  (2 * STAGE_PV * 4)           // 75776 B (2-stage)

// Scratch (static device memory; allocation-free per harness rules)
__device__ float g_S[3][BATCH * L * L];     // S natural; P stored tf32 + k-permuted
__device__ float g_Xw[3][BATCH * L * D];    // tf32(X * wM), k-permuted
__device__ float g_Yc[2][BATCH * L * D];    // tf32(enc_b), tf32(enc_c), natural
__device__ float g_r[3][2][BATCH * L];      // rX, rY per pair
__device__ float g_m[3][BATCH * L];         // row max per pair
__device__ float g_v[3][BATCH * D];         // b2a vector per pair

// ===========================================================================
// helpers
// ===========================================================================
__device__ __forceinline__ uint32_t f2tf(float f) {
    uint32_t r;
    asm("cvt.rna.tf32.f32 %0, %1;" : "=r"(r) : "f"(f));
    return r;
}
__device__ __forceinline__ float4 cvt4(float4 v) {
    v.x = __uint_as_float(f2tf(v.x));
    v.y = __uint_as_float(f2tf(v.y));
    v.z = __uint_as_float(f2tf(v.z));
    v.w = __uint_as_float(f2tf(v.w));
    return v;
}
// Within-8-group k permutation: positions [0..7] hold cols [0,4,1,5,2,6,3,7].
__device__ __forceinline__ float4 perm8(float4 v) {
    float4 q;
    q.x = __shfl_xor_sync(0xFFFFFFFFu, v.x, 1);
    q.y = __shfl_xor_sync(0xFFFFFFFFu, v.y, 1);
    q.z = __shfl_xor_sync(0xFFFFFFFFu, v.z, 1);
    q.w = __shfl_xor_sync(0xFFFFFFFFu, v.w, 1);
    return (threadIdx.x & 1) ? make_float4(q.z, v.z, q.w, v.w)
                             : make_float4(v.x, q.x, v.y, q.y);
}
__device__ __forceinline__ void mma8(float* c, const uint32_t* a, const uint32_t* b) {
    asm volatile(
        "mma.sync.aligned.m16n8k8.row.col.f32.tf32.tf32.f32 "
        "{%0,%1,%2,%3}, {%4,%5,%6,%7}, {%8,%9}, {%0,%1,%2,%3};"
        : "+f"(c[0]), "+f"(c[1]), "+f"(c[2]), "+f"(c[3])
        : "r"(a[0]), "r"(a[1]), "r"(a[2]), "r"(a[3]), "r"(b[0]), "r"(b[1]));
}
__device__ __forceinline__ void cp16(float* dst, const float* src) {
    uint32_t d = (uint32_t)__cvta_generic_to_shared(dst);
    asm volatile("cp.async.cg.shared.global [%0], [%1], 16;" :: "r"(d), "l"(src) : "memory");
}
__device__ __forceinline__ void cp_commit() {
    asm volatile("cp.async.commit_group;" ::: "memory");
}

// ===========================================================================
// prep: per encoder matrix: 2 row-dots + tf32 operand copies (unchanged)
// ===========================================================================
__global__ void prep_kernel(const float* __restrict__ ea, const float* __restrict__ eb,
                            const float* __restrict__ ec,
                            const float* __restrict__ wab, const float* __restrict__ wac,
                            const float* __restrict__ wbc) {
    int mat = blockIdx.y;
    int row = blockIdx.x * 8 + (threadIdx.x >> 5);
    int lane = threadIdx.x & 31;

    const float *src, *w1, *w2, *sc1, *sc2;
    float *r1, *r2, *d1, *d2;
    int p1, p2;
    if (mat == 0) {
        src = ea; w1 = wab; r1 = &g_r[0][0][0]; w2 = wac; r2 = &g_r[1][0][0];
        sc1 = wab + 1024; d1 = g_Xw[0]; p1 = 1;
        sc2 = wac + 1024; d2 = g_Xw[1]; p2 = 1;
    } else if (mat == 1) {
        src = eb; w1 = wab + 512; r1 = &g_r[0][1][0]; w2 = wbc; r2 = &g_r[2][0][0];
        sc1 = wbc + 1024; d1 = g_Xw[2]; p1 = 1;
        sc2 = nullptr; d2 = g_Yc[0]; p2 = 0;
    } else {
        src = ec; w1 = wac + 512; r1 = &g_r[1][1][0]; w2 = wbc + 512; r2 = &g_r[2][1][0];
        sc1 = nullptr; d1 = g_Yc[1]; p1 = 0;
        sc2 = nullptr; d2 = nullptr; p2 = 0;
    }

    const float* rp = src + (size_t)row * D;
    float4 x[4];
    float s1 = 0.f, s2 = 0.f;
#pragma unroll
    for (int t = 0; t < 4; t++) {
        int k = (t * 32 + lane) * 4;
        x[t] = *(const float4*)(rp + k);
        float4 a = *(const float4*)(w1 + k);
        s1 += x[t].x * a.x + x[t].y * a.y + x[t].z * a.z + x[t].w * a.w;
        float4 b = *(const float4*)(w2 + k);
        s2 += x[t].x * b.x + x[t].y * b.y + x[t].z * b.z + x[t].w * b.w;
    }
#pragma unroll
    for (int o = 16; o; o >>= 1) {
        s1 += __shfl_xor_sync(0xFFFFFFFFu, s1, o);
        s2 += __shfl_xor_sync(0xFFFFFFFFu, s2, o);
    }
    if (!lane) { r1[row] = s1; r2[row] = s2; }

#pragma unroll
    for (int t = 0; t < 4; t++) {
        int k = (t * 32 + lane) * 4;
        float4 v = x[t];
        if (sc1) {
            float4 s = *(const float4*)(sc1 + k);
            v.x *= s.x; v.y *= s.y; v.z *= s.z; v.w *= s.w;
        }
        v = cvt4(v);
        if (p1) v = perm8(v);
        *(float4*)(d1 + (size_t)row * D + k) = v;
    }
    if (d2) {
#pragma unroll
        for (int t = 0; t < 4; t++) {
            int k = (t * 32 + lane) * 4;
            float4 v = x[t];
            if (sc2) {
                float4 s = *(const float4*)(sc2 + k);
                v.x *= s.x; v.y *= s.y; v.z *= s.z; v.w *= s.w;
            }
            v = cvt4(v);
            if (p2) v = perm8(v);
            *(float4*)(d2 + (size_t)row * D + k) = v;
        }
    }
}

// ===========================================================================
// S GEMM (batched): S = rX + rY + Xw @ Yc^T.  grid (4,4,24), 256 threads,
// 8 warps 2x4, warp tile 64x32 (R8 config). ONE __syncthreads per chunk.
// ===========================================================================
__global__ __launch_bounds__(256, 2)
void gemm_s_mma(const float* __restrict__ dummy) {
    extern __shared__ float sm[];
    int pair = blockIdx.z >> 3, b = blockIdx.z & 7;
    int yt = (pair == 0) ? 0 : 1;
    int i0 = blockIdx.y * 128, j0 = blockIdx.x * 128;
    const float* Ag = g_Xw[pair] + ((size_t)b * L + i0) * D;
    const float* Bg = g_Yc[yt] + ((size_t)b * L + j0) * D;
    int tid = threadIdx.x;

    int lane = tid & 31, w = tid >> 5;
    int ar = lane >> 2, ac = lane & 3;
    int mbase = (w & 1) * 64, nbase = (w >> 1) * 32;
    float acc[4][4][4] = {};

    auto issue = [&](int c, int st) {
        float* As = sm + st * STAGE_S;
        float* Bs = As + 128 * LDA;
        int k0 = c * 32;
#pragma unroll
        for (int it = 0; it < 4; it++) {
            int i = it * 256 + tid;
            int row = i >> 3, c4 = (i & 7) << 2;
            cp16(As + row * LDA + c4, Ag + (size_t)row * D + k0 + c4);
            cp16(Bs + row * LDA + c4, Bg + (size_t)row * D + k0 + c4);
        }
        cp_commit();
    };

    issue(0, 0);
    for (int c = 0; c < NCHUNK; c++) {
        asm volatile("cp.async.wait_group 0;" ::: "memory");
        __syncthreads();                       // publishes chunk c; guards stage reuse
        if (c + 1 < NCHUNK) issue(c + 1, (c + 1) & 1);
        const float* a_s = sm + (c & 1) * STAGE_S;
        const float* b_s = a_s + 128 * LDA;
#pragma unroll
        for (int ks = 0; ks < 4; ks++) {
            uint32_t af[4][4], bf[4][2];
#pragma unroll
            for (int mt = 0; mt < 4; mt++) {
                const float* p = a_s + (mbase + mt * 16 + ar) * LDA + ks * 8 + ac * 2;
                float2 a0 = *(const float2*)p;
                float2 a1 = *(const float2*)(p + 8 * LDA);
                af[mt][0] = __float_as_uint(a0.x);
                af[mt][1] = __float_as_uint(a1.x);
                af[mt][2] = __float_as_uint(a0.y);
                af[mt][3] = __float_as_uint(a1.y);
            }
#pragma unroll
            for (int nt = 0; nt < 4; nt++) {
                const float* q = b_s + (nbase + nt * 8 + ar) * LDA + ks * 8 + ac;
                bf[nt][0] = __float_as_uint(q[0]);
                bf[nt][1] = __float_as_uint(q[4]);
            }
#pragma unroll
            for (int mt = 0; mt < 4; mt++)
#pragma unroll
                for (int nt = 0; nt < 4; nt++) mma8(acc[mt][nt], af[mt], bf[nt]);
        }
    }

    const float* rx = g_r[pair][0] + b * L + i0;
    const float* ry = g_r[pair][1] + b * L + j0;
    float* Sp = g_S[pair] + ((size_t)b * L + i0) * L + j0;
#pragma unroll
    for (int mt = 0; mt < 4; mt++) {
        int r = mbase + mt * 16 + ar;
        float rx0 = rx[r], rx1 = rx[r + 8];
#pragma unroll
        for (int nt = 0; nt < 4; nt++) {
            int cI = nbase + nt * 8 + ac * 2;
            float ry0 = ry[cI], ry1 = ry[cI + 1];
            float2 v0 = make_float2(acc[mt][nt][0] + rx0 + ry0, acc[mt][nt][1] + rx0 + ry1);
            float2 v1 = make_float2(acc[mt][nt][2] + rx1 + ry0, acc[mt][nt][3] + rx1 + ry1);
            *(float2*)(Sp + (size_t)r * L + cI) = v0;
            *(float2*)(Sp + (size_t)(r + 8) * L + cI) = v1;
        }
    }
}

// ===========================================================================
// PV GEMM (batched): O = P @ Yc; fused concat writes.  grid (4,4,24),
// 256 threads, warp tile 64x32. ONE __syncthreads per chunk.
// ===========================================================================
__constant__ int c_secRowA[3] = {0, 0, 512};
__constant__ int c_offRawA[3] = {512, 1024, 1024};
__constant__ int c_offProdA[3] = {1536, 2048, 2048};

__global__ __launch_bounds__(256, 2)
void gemm_pv_mma(const float* __restrict__ ea, const float* __restrict__ eb,
                 const float* __restrict__ ec, float* __restrict__ out) {
    extern __shared__ float sm[];
    int pair = blockIdx.z >> 3, b = blockIdx.z & 7;
    int yt = (pair == 0) ? 0 : 1;
    const float* E = (pair == 2) ? eb : ea;
    int secRow = c_secRowA[pair], offRaw = c_offRawA[pair], offProd = c_offProdA[pair];
    int i0 = blockIdx.y * 128, d0 = blockIdx.x * 128;
    const float* Ag = g_S[pair] + ((size_t)b * L + i0) * L;
    const float* Bg = g_Yc[yt] + (size_t)b * L * D + d0;
    int tid = threadIdx.x;

    int lane = tid & 31, w = tid >> 5;
    int ar = lane >> 2, ac = lane & 3;
    int mbase = (w & 1) * 64, nbase = (w >> 1) * 32;
    float acc[4][4][4] = {};

    auto issue = [&](int c, int st) {
        float* As = sm + st * STAGE_PV;
        float* Bs = As + 128 * LDA;
        int k0 = c * 32;
#pragma unroll
        for (int it = 0; it < 4; it++) {
            int i = it * 256 + tid;
            int arow = i >> 3, ac4 = (i & 7) << 2;
            cp16(As + arow * LDA + ac4, Ag + (size_t)arow * L + k0 + ac4);
            int brow = i >> 5, bc4 = (i & 31) << 2;
            cp16(Bs + brow * LDBPV + bc4, Bg + (size_t)(k0 + brow) * D + bc4);
        }
        cp_commit();
    };

    issue(0, 0);
    for (int c = 0; c < NCHUNK; c++) {
        asm volatile("cp.async.wait_group 0;" ::: "memory");
        __syncthreads();                       // publishes chunk c; guards stage reuse
        if (c + 1 < NCHUNK) issue(c + 1, (c + 1) & 1);
        const float* a_s = sm + (c & 1) * STAGE_PV;
        const float* b_s = a_s + 128 * LDA;
#pragma unroll
        for (int ks = 0; ks < 4; ks++) {
            uint32_t af[4][4], bf[4][2];
#pragma unroll
            for (int mt = 0; mt < 4; mt++) {
                const float* p = a_s + (mbase + mt * 16 + ar) * LDA + ks * 8 + ac * 2;
                float2 a0 = *(const float2*)p;
                float2 a1 = *(const float2*)(p + 8 * LDA);
                af[mt][0] = __float_as_uint(a0.x);
                af[mt][1] = __float_as_uint(a1.x);
                af[mt][2] = __float_as_uint(a0.y);
                af[mt][3] = __float_as_uint(a1.y);
            }
#pragma unroll
            for (int nt = 0; nt < 4; nt++) {
                const float* q = b_s + (ks * 8 + ac) * LDBPV + nbase + nt * 8 + ar;
                bf[nt][0] = __float_as_uint(q[0]);
                bf[nt][1] = __float_as_uint(q[4 * LDBPV]);
            }
#pragma unroll
            for (int mt = 0; mt < 4; mt++)
#pragma unroll
                for (int nt = 0; nt < 4; nt++) mma8(acc[mt][nt], af[mt], bf[nt]);
        }
    }

#pragma unroll
    for (int mt = 0; mt < 4; mt++) {
        int r = mbase + mt * 16 + ar;
        int i = i0 + r;
        const float* e0p = E + ((size_t)b * L + i) * D + d0;
        float* o0p = out + ((size_t)b * OUTR + secRow + i) * OUTC;
#pragma unroll
        for (int nt = 0; nt < 4; nt++) {
            int cI = nbase + nt * 8 + ac * 2;
            float2 e0 = *(const float2*)(e0p + cI);
            float2 e1 = *(const float2*)(e0p + 8 * D + cI);
            float2 v0 = make_float2(acc[mt][nt][0], acc[mt][nt][1]);
            float2 v1 = make_float2(acc[mt][nt][2], acc[mt][nt][3]);
            *(float2*)(o0p + offRaw + d0 + cI) = v0;
            *(float2*)(o0p + 8 * OUTC + offRaw + d0 + cI) = v1;
            *(float2*)(o0p + offProd + d0 + cI) = make_float2(v0.x * e0.x, v0.y * e0.y);
            *(float2*)(o0p + 8 * OUTC + offProd + d0 + cI) = make_float2(v1.x * e1.x, v1.y * e1.y);
        }
    }
}

// ===========================================================================
// softmax (batched): in-place row softmax; P stored tf32 + k-permuted. grid (512,3)
// ===========================================================================
__global__ void softmax_kernel(const float* __restrict__ dummy) {
    int pair = blockIdx.y;
    int row = blockIdx.x * 8 + (threadIdx.x >> 5);
    int lane = threadIdx.x & 31;
    float* r = g_S[pair] + (size_t)row * L;
    float4 v[4];
    float mx = -1e30f;
#pragma unroll
    for (int t = 0; t < 4; t++) {
        v[t] = ((float4*)r)[t * 32 + lane];
        mx = fmaxf(mx, fmaxf(fmaxf(v[t].x, v[t].y), fmaxf(v[t].z, v[t].w)));
    }
#pragma unroll
    for (int o = 16; o; o >>= 1) mx = fmaxf(mx, __shfl_xor_sync(0xFFFFFFFFu, mx, o));
    float s = 0.f;
#pragma unroll
    for (int t = 0; t < 4; t++) {
        v[t].x = __expf(v[t].x - mx);
        v[t].y = __expf(v[t].y - mx);
        v[t].z = __expf(v[t].z - mx);
        v[t].w = __expf(v[t].w - mx);
        s += v[t].x + v[t].y + v[t].z + v[t].w;
    }
#pragma unroll
    for (int o = 16; o; o >>= 1) s += __shfl_xor_sync(0xFFFFFFFFu, s, o);
    float inv = 1.f / s;
#pragma unroll
    for (int t = 0; t < 4; t++) {
        v[t].x *= inv; v[t].y *= inv; v[t].z *= inv; v[t].w *= inv;
        ((float4*)r)[t * 32 + lane] = perm8(cvt4(v[t]));
    }
    if (!lane) g_m[pair][row] = mx;
}

// ===========================================================================
// beta (batched): beta = softmax_i(m); v = sum_i beta_i * X[b,i,:]. grid (8,3)
// ===========================================================================
__global__ __launch_bounds__(512)
void beta_b2a_kernel(const float* __restrict__ ea, const float* __restrict__ eb,
                     const float* __restrict__ ec) {
    int b = blockIdx.x, pair = blockIdx.y, t = threadIdx.x;
    const float* X = (pair == 2) ? eb : ea;
    int lane = t & 31, wid = t >> 5;
    __shared__ float sb[512];
    __shared__ float redm[16];
    __shared__ float reds[16];
    __shared__ float bc[2];
    float mv = g_m[pair][b * L + t];
    float v = mv;
#pragma unroll
    for (int o = 16; o; o >>= 1) v = fmaxf(v, __shfl_xor_sync(0xFFFFFFFFu, v, o));
    if (!lane) redm[wid] = v;
    __syncthreads();
    if (t == 0) {
        float m2 = redm[0];
        for (int i = 1; i < 16; i++) m2 = fmaxf(m2, redm[i]);
        bc[0] = m2;
    }
    __syncthreads();
    float mx = bc[0];
    float e = __expf(mv - mx);
    v = e;
#pragma unroll
    for (int o = 16; o; o >>= 1) v += __shfl_xor_sync(0xFFFFFFFFu, v, o);
    if (!lane) reds[wid] = v;
    __syncthreads();
    if (t == 0) {
        float s = 0.f;
        for (int i = 0; i < 16; i++) s += reds[i];
        bc[1] = s;
    }
    __syncthreads();
    sb[t] = e / bc[1];
    __syncthreads();
    const float* Xb = X + (size_t)b * L * D;
    float acc = 0.f;
#pragma unroll 8
    for (int i = 0; i < L; i++) acc += sb[i] * Xb[(size_t)i * D + t];
    g_v[pair][b * D + t] = acc;
}

// ===========================================================================
// tail: fused enc copy + vector broadcast (raw + E*vec). grid (512, 8, 3)
// ===========================================================================
__global__ void tail_kernel(const float* __restrict__ ea, const float* __restrict__ eb,
                            const float* __restrict__ ec, float* __restrict__ out) {
    int s = blockIdx.z, b = blockIdx.y, r = blockIdx.x;
    const float* E = (s == 0) ? ea : (s == 1) ? eb : ec;
    int t = threadIdx.x;
    float4 e = ((const float4*)(E + ((size_t)b * L + r) * D))[t];
    float* row = out + ((size_t)b * OUTR + s * 512 + r) * OUTC;
    ((float4*)row)[t] = e;
    if (s == 1) {
        float4 vv = ((const float4*)(&g_v[0][b * D]))[t];
        ((float4*)(row + 512))[t] = vv;
        ((float4*)(row + 1536))[t] = make_float4(vv.x * e.x, vv.y * e.y, vv.z * e.z, vv.w * e.w);
    } else if (s == 2) {
        float4 v1 = ((const float4*)(&g_v[1][b * D]))[t];
        ((float4*)(row + 512))[t] = v1;
        ((float4*)(row + 1536))[t] = make_float4(v1.x * e.x, v1.y * e.y, v1.z * e.z, v1.w * e.w);
        float4 v2 = ((const float4*)(&g_v[2][b * D]))[t];
        ((float4*)(row + 1024))[t] = v2;
        ((float4*)(row + 2048))[t] = make_float4(v2.x * e.x, v2.y * e.y, v2.z * e.z, v2.w * e.w);
    }
}

// ===========================================================================
extern "C" void kernel_launch(void* const* d_in, const int* in_sizes, int n_in,
                              void* d_out, int out_size) {
    const float* ea = (const float*)d_in[0];
    const float* eb = (const float*)d_in[1];
    const float* ec = (const float*)d_in[2];
    const float* wab = (const float*)d_in[3];
    const float* wac = (const float*)d_in[4];
    const float* wbc = (const float*)d_in[5];
    float* out = (float*)d_out;

    cudaFuncSetAttribute(gemm_s_mma, cudaFuncAttributeMaxDynamicSharedMemorySize, SMEM_S);
    cudaFuncSetAttribute(gemm_pv_mma, cudaFuncAttributeMaxDynamicSharedMemorySize, SMEM_PV);

    prep_kernel<<<dim3(512, 3), 256>>>(ea, eb, ec, wab, wac, wbc);
    gemm_s_mma<<<dim3(4, 4, 24), 256, SMEM_S>>>(nullptr);
    softmax_kernel<<<dim3(512, 3), 256>>>(nullptr);
    gemm_pv_mma<<<dim3(4, 4, 24), 256, SMEM_PV>>>(ea, eb, ec, out);
    beta_b2a_kernel<<<dim3(8, 3), 512>>>(ea, eb, ec);
    tail_kernel<<<dim3(512, 8, 3), 128>>>(ea, eb, ec, out);
}

// round 11
// speedup vs baseline: 1.1770x; 1.1651x over previous
#include <cuda_runtime.h>
#include <cstdint>

#define BATCH 8
#define L 512
#define D 512
#define OUTR 1536
#define OUTC 2560
#define NCHUNK 16
#define LDA 40     // [row][k] smem stride (floats)
#define LDBPV 136  // [k][n] smem stride for PV B (floats)

// Stage sizes (floats)
#define STAGE_S  (2 * 128 * LDA)              // 10240
#define STAGE_PV (128 * LDA + 32 * LDBPV)     // 9472
#define SMEM_S   (2 * STAGE_S * 4)            // 81920 B (2-stage)
#define SMEM_PV  (2 * STAGE_PV * 4)           // 75776 B (2-stage)

// Scratch (static device memory; allocation-free per harness rules)
__device__ float g_S[3][BATCH * L * L];     // S natural; P stored tf32 + k-permuted
__device__ float g_Xw[3][BATCH * L * D];    // tf32(X * wM), k-permuted
__device__ float g_Yc[2][BATCH * L * D];    // tf32(enc_b), tf32(enc_c), natural
__device__ float g_r[3][2][BATCH * L];      // rX, rY per pair
__device__ float g_m[3][BATCH * L];         // row max per pair
__device__ float g_v[3][BATCH * D];         // b2a vector per pair

// ===========================================================================
// helpers
// ===========================================================================
__device__ __forceinline__ uint32_t f2tf(float f) {
    uint32_t r;
    asm("cvt.rna.tf32.f32 %0, %1;" : "=r"(r) : "f"(f));
    return r;
}
__device__ __forceinline__ float4 cvt4(float4 v) {
    v.x = __uint_as_float(f2tf(v.x));
    v.y = __uint_as_float(f2tf(v.y));
    v.z = __uint_as_float(f2tf(v.z));
    v.w = __uint_as_float(f2tf(v.w));
    return v;
}
// Within-8-group k permutation: positions [0..7] hold cols [0,4,1,5,2,6,3,7].
__device__ __forceinline__ float4 perm8(float4 v) {
    float4 q;
    q.x = __shfl_xor_sync(0xFFFFFFFFu, v.x, 1);
    q.y = __shfl_xor_sync(0xFFFFFFFFu, v.y, 1);
    q.z = __shfl_xor_sync(0xFFFFFFFFu, v.z, 1);
    q.w = __shfl_xor_sync(0xFFFFFFFFu, v.w, 1);
    return (threadIdx.x & 1) ? make_float4(q.z, v.z, q.w, v.w)
                             : make_float4(v.x, q.x, v.y, q.y);
}
__device__ __forceinline__ void mma8(float* c, const uint32_t* a, const uint32_t* b) {
    asm volatile(
        "mma.sync.aligned.m16n8k8.row.col.f32.tf32.tf32.f32 "
        "{%0,%1,%2,%3}, {%4,%5,%6,%7}, {%8,%9}, {%0,%1,%2,%3};"
        : "+f"(c[0]), "+f"(c[1]), "+f"(c[2]), "+f"(c[3])
        : "r"(a[0]), "r"(a[1]), "r"(a[2]), "r"(a[3]), "r"(b[0]), "r"(b[1]));
}
__device__ __forceinline__ void cp16(float* dst, const float* src) {
    uint32_t d = (uint32_t)__cvta_generic_to_shared(dst);
    asm volatile("cp.async.cg.shared.global [%0], [%1], 16;" :: "r"(d), "l"(src) : "memory");
}
__device__ __forceinline__ void cp_commit() {
    asm volatile("cp.async.commit_group;" ::: "memory");
}

// ===========================================================================
// prep: per encoder matrix: 2 row-dots + tf32 operand copies + enc->out copy
// grid (512, 3), 256 threads
// ===========================================================================
__global__ void prep_kernel(const float* __restrict__ ea, const float* __restrict__ eb,
                            const float* __restrict__ ec,
                            const float* __restrict__ wab, const float* __restrict__ wac,
                            const float* __restrict__ wbc, float* __restrict__ out) {
    int mat = blockIdx.y;
    int row = blockIdx.x * 8 + (threadIdx.x >> 5);
    int lane = threadIdx.x & 31;

    const float *src, *w1, *w2, *sc1, *sc2;
    float *r1, *r2, *d1, *d2;
    int p1, p2;
    if (mat == 0) {
        src = ea; w1 = wab; r1 = &g_r[0][0][0]; w2 = wac; r2 = &g_r[1][0][0];
        sc1 = wab + 1024; d1 = g_Xw[0]; p1 = 1;
        sc2 = wac + 1024; d2 = g_Xw[1]; p2 = 1;
    } else if (mat == 1) {
        src = eb; w1 = wab + 512; r1 = &g_r[0][1][0]; w2 = wbc; r2 = &g_r[2][0][0];
        sc1 = wbc + 1024; d1 = g_Xw[2]; p1 = 1;
        sc2 = nullptr; d2 = g_Yc[0]; p2 = 0;
    } else {
        src = ec; w1 = wac + 512; r1 = &g_r[1][1][0]; w2 = wbc + 512; r2 = &g_r[2][1][0];
        sc1 = nullptr; d1 = g_Yc[1]; p1 = 0;
        sc2 = nullptr; d2 = nullptr; p2 = 0;
    }

    const float* rp = src + (size_t)row * D;
    float4 x[4];
    float s1 = 0.f, s2 = 0.f;
#pragma unroll
    for (int t = 0; t < 4; t++) {
        int k = (t * 32 + lane) * 4;
        x[t] = *(const float4*)(rp + k);
        float4 a = *(const float4*)(w1 + k);
        s1 += x[t].x * a.x + x[t].y * a.y + x[t].z * a.z + x[t].w * a.w;
        float4 b = *(const float4*)(w2 + k);
        s2 += x[t].x * b.x + x[t].y * b.y + x[t].z * b.z + x[t].w * b.w;
    }
#pragma unroll
    for (int o = 16; o; o >>= 1) {
        s1 += __shfl_xor_sync(0xFFFFFFFFu, s1, o);
        s2 += __shfl_xor_sync(0xFFFFFFFFu, s2, o);
    }
    if (!lane) { r1[row] = s1; r2[row] = s2; }

    // fused encoder copy into output section `mat` (raw fp32 values)
    {
        int b = row >> 9, r = row & 511;
        float* orow = out + ((size_t)b * OUTR + mat * 512 + r) * OUTC;
#pragma unroll
        for (int t = 0; t < 4; t++) {
            int k = (t * 32 + lane) * 4;
            *(float4*)(orow + k) = x[t];
        }
    }

#pragma unroll
    for (int t = 0; t < 4; t++) {
        int k = (t * 32 + lane) * 4;
        float4 v = x[t];
        if (sc1) {
            float4 s = *(const float4*)(sc1 + k);
            v.x *= s.x; v.y *= s.y; v.z *= s.z; v.w *= s.w;
        }
        v = cvt4(v);
        if (p1) v = perm8(v);
        *(float4*)(d1 + (size_t)row * D + k) = v;
    }
    if (d2) {
#pragma unroll
        for (int t = 0; t < 4; t++) {
            int k = (t * 32 + lane) * 4;
            float4 v = x[t];
            if (sc2) {
                float4 s = *(const float4*)(sc2 + k);
                v.x *= s.x; v.y *= s.y; v.z *= s.z; v.w *= s.w;
            }
            v = cvt4(v);
            if (p2) v = perm8(v);
            *(float4*)(d2 + (size_t)row * D + k) = v;
        }
    }
}

// ===========================================================================
// S GEMM (per pair): S = rX + rY + Xw @ Yc^T.  grid (4,4,8) z = b
// R10 internals (8 warps 2x4, warp tile 64x32, single-sync 2-stage loop).
// ===========================================================================
__global__ __launch_bounds__(256, 2)
void gemm_s_mma(int pair, int yt) {
    extern __shared__ float sm[];
    int b = blockIdx.z;
    int i0 = blockIdx.y * 128, j0 = blockIdx.x * 128;
    const float* Ag = g_Xw[pair] + ((size_t)b * L + i0) * D;
    const float* Bg = g_Yc[yt] + ((size_t)b * L + j0) * D;
    int tid = threadIdx.x;

    int lane = tid & 31, w = tid >> 5;
    int ar = lane >> 2, ac = lane & 3;
    int mbase = (w & 1) * 64, nbase = (w >> 1) * 32;
    float acc[4][4][4] = {};

    auto issue = [&](int c, int st) {
        float* As = sm + st * STAGE_S;
        float* Bs = As + 128 * LDA;
        int k0 = c * 32;
#pragma unroll
        for (int it = 0; it < 4; it++) {
            int i = it * 256 + tid;
            int row = i >> 3, c4 = (i & 7) << 2;
            cp16(As + row * LDA + c4, Ag + (size_t)row * D + k0 + c4);
            cp16(Bs + row * LDA + c4, Bg + (size_t)row * D + k0 + c4);
        }
        cp_commit();
    };

    issue(0, 0);
    for (int c = 0; c < NCHUNK; c++) {
        asm volatile("cp.async.wait_group 0;" ::: "memory");
        __syncthreads();
        if (c + 1 < NCHUNK) issue(c + 1, (c + 1) & 1);
        const float* a_s = sm + (c & 1) * STAGE_S;
        const float* b_s = a_s + 128 * LDA;
#pragma unroll
        for (int ks = 0; ks < 4; ks++) {
            uint32_t af[4][4], bf[4][2];
#pragma unroll
            for (int mt = 0; mt < 4; mt++) {
                const float* p = a_s + (mbase + mt * 16 + ar) * LDA + ks * 8 + ac * 2;
                float2 a0 = *(const float2*)p;
                float2 a1 = *(const float2*)(p + 8 * LDA);
                af[mt][0] = __float_as_uint(a0.x);
                af[mt][1] = __float_as_uint(a1.x);
                af[mt][2] = __float_as_uint(a0.y);
                af[mt][3] = __float_as_uint(a1.y);
            }
#pragma unroll
            for (int nt = 0; nt < 4; nt++) {
                const float* q = b_s + (nbase + nt * 8 + ar) * LDA + ks * 8 + ac;
                bf[nt][0] = __float_as_uint(q[0]);
                bf[nt][1] = __float_as_uint(q[4]);
            }
#pragma unroll
            for (int mt = 0; mt < 4; mt++)
#pragma unroll
                for (int nt = 0; nt < 4; nt++) mma8(acc[mt][nt], af[mt], bf[nt]);
        }
    }

    const float* rx = g_r[pair][0] + b * L + i0;
    const float* ry = g_r[pair][1] + b * L + j0;
    float* Sp = g_S[pair] + ((size_t)b * L + i0) * L + j0;
#pragma unroll
    for (int mt = 0; mt < 4; mt++) {
        int r = mbase + mt * 16 + ar;
        float rx0 = rx[r], rx1 = rx[r + 8];
#pragma unroll
        for (int nt = 0; nt < 4; nt++) {
            int cI = nbase + nt * 8 + ac * 2;
            float ry0 = ry[cI], ry1 = ry[cI + 1];
            float2 v0 = make_float2(acc[mt][nt][0] + rx0 + ry0, acc[mt][nt][1] + rx0 + ry1);
            float2 v1 = make_float2(acc[mt][nt][2] + rx1 + ry0, acc[mt][nt][3] + rx1 + ry1);
            *(float2*)(Sp + (size_t)r * L + cI) = v0;
            *(float2*)(Sp + (size_t)(r + 8) * L + cI) = v1;
        }
    }
}

// ===========================================================================
// PV GEMM (per pair): O = P @ Yc; fused concat writes.  grid (4,4,8) z = b
// ===========================================================================
__global__ __launch_bounds__(256, 2)
void gemm_pv_mma(int pair, int yt, const float* __restrict__ E, float* __restrict__ out,
                 int secRow, int offRaw, int offProd) {
    extern __shared__ float sm[];
    int b = blockIdx.z;
    int i0 = blockIdx.y * 128, d0 = blockIdx.x * 128;
    const float* Ag = g_S[pair] + ((size_t)b * L + i0) * L;
    const float* Bg = g_Yc[yt] + (size_t)b * L * D + d0;
    int tid = threadIdx.x;

    int lane = tid & 31, w = tid >> 5;
    int ar = lane >> 2, ac = lane & 3;
    int mbase = (w & 1) * 64, nbase = (w >> 1) * 32;
    float acc[4][4][4] = {};

    auto issue = [&](int c, int st) {
        float* As = sm + st * STAGE_PV;
        float* Bs = As + 128 * LDA;
        int k0 = c * 32;
#pragma unroll
        for (int it = 0; it < 4; it++) {
            int i = it * 256 + tid;
            int arow = i >> 3, ac4 = (i & 7) << 2;
            cp16(As + arow * LDA + ac4, Ag + (size_t)arow * L + k0 + ac4);
            int brow = i >> 5, bc4 = (i & 31) << 2;
            cp16(Bs + brow * LDBPV + bc4, Bg + (size_t)(k0 + brow) * D + bc4);
        }
        cp_commit();
    };

    issue(0, 0);
    for (int c = 0; c < NCHUNK; c++) {
        asm volatile("cp.async.wait_group 0;" ::: "memory");
        __syncthreads();
        if (c + 1 < NCHUNK) issue(c + 1, (c + 1) & 1);
        const float* a_s = sm + (c & 1) * STAGE_PV;
        const float* b_s = a_s + 128 * LDA;
#pragma unroll
        for (int ks = 0; ks < 4; ks++) {
            uint32_t af[4][4], bf[4][2];
#pragma unroll
            for (int mt = 0; mt < 4; mt++) {
                const float* p = a_s + (mbase + mt * 16 + ar) * LDA + ks * 8 + ac * 2;
                float2 a0 = *(const float2*)p;
                float2 a1 = *(const float2*)(p + 8 * LDA);
                af[mt][0] = __float_as_uint(a0.x);
                af[mt][1] = __float_as_uint(a1.x);
                af[mt][2] = __float_as_uint(a0.y);
                af[mt][3] = __float_as_uint(a1.y);
            }
#pragma unroll
            for (int nt = 0; nt < 4; nt++) {
                const float* q = b_s + (ks * 8 + ac) * LDBPV + nbase + nt * 8 + ar;
                bf[nt][0] = __float_as_uint(q[0]);
                bf[nt][1] = __float_as_uint(q[4 * LDBPV]);
            }
#pragma unroll
            for (int mt = 0; mt < 4; mt++)
#pragma unroll
                for (int nt = 0; nt < 4; nt++) mma8(acc[mt][nt], af[mt], bf[nt]);
        }
    }

#pragma unroll
    for (int mt = 0; mt < 4; mt++) {
        int r = mbase + mt * 16 + ar;
        int i = i0 + r;
        const float* e0p = E + ((size_t)b * L + i) * D + d0;
        float* o0p = out + ((size_t)b * OUTR + secRow + i) * OUTC;
#pragma unroll
        for (int nt = 0; nt < 4; nt++) {
            int cI = nbase + nt * 8 + ac * 2;
            float2 e0 = *(const float2*)(e0p + cI);
            float2 e1 = *(const float2*)(e0p + 8 * D + cI);
            float2 v0 = make_float2(acc[mt][nt][0], acc[mt][nt][1]);
            float2 v1 = make_float2(acc[mt][nt][2], acc[mt][nt][3]);
            *(float2*)(o0p + offRaw + d0 + cI) = v0;
            *(float2*)(o0p + 8 * OUTC + offRaw + d0 + cI) = v1;
            *(float2*)(o0p + offProd + d0 + cI) = make_float2(v0.x * e0.x, v0.y * e0.y);
            *(float2*)(o0p + 8 * OUTC + offProd + d0 + cI) = make_float2(v1.x * e1.x, v1.y * e1.y);
        }
    }
}

// ===========================================================================
// softmax (per pair): in-place row softmax; P stored tf32 + k-permuted. grid (512)
// ===========================================================================
__global__ void softmax_kernel(int pair) {
    int row = blockIdx.x * 8 + (threadIdx.x >> 5);
    int lane = threadIdx.x & 31;
    float* r = g_S[pair] + (size_t)row * L;
    float4 v[4];
    float mx = -1e30f;
#pragma unroll
    for (int t = 0; t < 4; t++) {
        v[t] = ((float4*)r)[t * 32 + lane];
        mx = fmaxf(mx, fmaxf(fmaxf(v[t].x, v[t].y), fmaxf(v[t].z, v[t].w)));
    }
#pragma unroll
    for (int o = 16; o; o >>= 1) mx = fmaxf(mx, __shfl_xor_sync(0xFFFFFFFFu, mx, o));
    float s = 0.f;
#pragma unroll
    for (int t = 0; t < 4; t++) {
        v[t].x = __expf(v[t].x - mx);
        v[t].y = __expf(v[t].y - mx);
        v[t].z = __expf(v[t].z - mx);
        v[t].w = __expf(v[t].w - mx);
        s += v[t].x + v[t].y + v[t].z + v[t].w;
    }
#pragma unroll
    for (int o = 16; o; o >>= 1) s += __shfl_xor_sync(0xFFFFFFFFu, s, o);
    float inv = 1.f / s;
#pragma unroll
    for (int t = 0; t < 4; t++) {
        v[t].x *= inv; v[t].y *= inv; v[t].z *= inv; v[t].w *= inv;
        ((float4*)r)[t * 32 + lane] = perm8(cvt4(v[t]));
    }
    if (!lane) g_m[pair][row] = mx;
}

// ===========================================================================
// beta (per pair): beta = softmax_i(m); v = sum_i beta_i * X[b,i,:]. grid (8)
// ===========================================================================
__global__ __launch_bounds__(512)
void beta_b2a_kernel(int pair, const float* __restrict__ X) {
    int b = blockIdx.x, t = threadIdx.x;
    int lane = t & 31, wid = t >> 5;
    __shared__ float sb[512];
    __shared__ float redm[16];
    __shared__ float reds[16];
    __shared__ float bc[2];
    float mv = g_m[pair][b * L + t];
    float v = mv;
#pragma unroll
    for (int o = 16; o; o >>= 1) v = fmaxf(v, __shfl_xor_sync(0xFFFFFFFFu, v, o));
    if (!lane) redm[wid] = v;
    __syncthreads();
    if (t == 0) {
        float m2 = redm[0];
        for (int i = 1; i < 16; i++) m2 = fmaxf(m2, redm[i]);
        bc[0] = m2;
    }
    __syncthreads();
    float mx = bc[0];
    float e = __expf(mv - mx);
    v = e;
#pragma unroll
    for (int o = 16; o; o >>= 1) v += __shfl_xor_sync(0xFFFFFFFFu, v, o);
    if (!lane) reds[wid] = v;
    __syncthreads();
    if (t == 0) {
        float s = 0.f;
        for (int i = 0; i < 16; i++) s += reds[i];
        bc[1] = s;
    }
    __syncthreads();
    sb[t] = e / bc[1];
    __syncthreads();
    const float* Xb = X + (size_t)b * L * D;
    float acc = 0.f;
#pragma unroll 8
    for (int i = 0; i < L; i++) acc += sb[i] * Xb[(size_t)i * D + t];
    g_v[pair][b * D + t] = acc;
}

// ===========================================================================
// bcast (per pair): vec + E*vec into Y-side section. grid (512, 8)
// ===========================================================================
__global__ void bcast_kernel(int pair, const float* __restrict__ E, float* __restrict__ out,
                             int secRow, int offRaw, int offProd) {
    int b = blockIdx.y, r = blockIdx.x;
    int t = threadIdx.x;
    float4 vv = ((const float4*)(&g_v[pair][b * D]))[t];
    float4 ee = ((const float4*)(E + ((size_t)b * L + r) * D))[t];
    float* row = out + ((size_t)b * OUTR + secRow + r) * OUTC;
    ((float4*)(row + offRaw))[t] = vv;
    float4 p = make_float4(vv.x * ee.x, vv.y * ee.y, vv.z * ee.z, vv.w * ee.w);
    ((float4*)(row + offProd))[t] = p;
}

// ===========================================================================
extern "C" void kernel_launch(void* const* d_in, const int* in_sizes, int n_in,
                              void* d_out, int out_size) {
    const float* ea = (const float*)d_in[0];
    const float* eb = (const float*)d_in[1];
    const float* ec = (const float*)d_in[2];
    const float* wab = (const float*)d_in[3];
    const float* wac = (const float*)d_in[4];
    const float* wbc = (const float*)d_in[5];
    float* out = (float*)d_out;

    // one-time host-resource init (streams/events; no device memory)
    static cudaStream_t st[3];
    static cudaEvent_t evPrep, evDone[3];
    static bool inited = false;
    if (!inited) {
        for (int i = 0; i < 3; i++) cudaStreamCreateWithFlags(&st[i], cudaStreamNonBlocking);
        cudaEventCreateWithFlags(&evPrep, cudaEventDisableTiming);
        for (int i = 0; i < 3; i++) cudaEventCreateWithFlags(&evDone[i], cudaEventDisableTiming);
        cudaFuncSetAttribute(gemm_s_mma, cudaFuncAttributeMaxDynamicSharedMemorySize, SMEM_S);
        cudaFuncSetAttribute(gemm_pv_mma, cudaFuncAttributeMaxDynamicSharedMemorySize, SMEM_PV);
        inited = true;
    }

    struct PairCfg {
        const float *X, *Y; int yt;
        int secRowA, offRawA, offProdA;   // PV destination (X-side section)
        int secRowV, offRawV, offProdV;   // bcast destination (Y-side section)
    };
    const PairCfg cfg[3] = {
        {ea, eb, 0,   0,  512, 1536,   512,  512, 1536},  // ab
        {ea, ec, 1,   0, 1024, 2048,  1024,  512, 1536},  // ac
        {eb, ec, 1, 512, 1024, 2048,  1024, 1024, 2048},  // bc
    };

    prep_kernel<<<dim3(512, 3), 256>>>(ea, eb, ec, wab, wac, wbc, out);
    cudaEventRecord(evPrep, 0);

    for (int p = 0; p < 3; p++) {
        cudaStreamWaitEvent(st[p], evPrep, 0);
        gemm_s_mma<<<dim3(4, 4, 8), 256, SMEM_S, st[p]>>>(p, cfg[p].yt);
        softmax_kernel<<<512, 256, 0, st[p]>>>(p);
        gemm_pv_mma<<<dim3(4, 4, 8), 256, SMEM_PV, st[p]>>>(
            p, cfg[p].yt, cfg[p].X, out, cfg[p].secRowA, cfg[p].offRawA, cfg[p].offProdA);
        beta_b2a_kernel<<<8, 512, 0, st[p]>>>(p, cfg[p].X);
        bcast_kernel<<<dim3(512, 8), 128, 0, st[p]>>>(
            p, cfg[p].Y, out, cfg[p].secRowV, cfg[p].offRawV, cfg[p].offProdV);
        cudaEventRecord(evDone[p], st[p]);
    }
    for (int p = 0; p < 3; p++) cudaStreamWaitEvent(0, evDone[p], 0);
}

// round 14
// speedup vs baseline: 1.1943x; 1.0147x over previous
#include <cuda_runtime.h>
#include <cuda_bf16.h>
#include <cstdint>

#define BATCH 8
#define L 512
#define D 512
#define OUTR 1536
#define OUTC 2560
#define NCHUNK 16

// bf16 S-GEMM smem geometry
#define RSW 96                         // smem row stride bytes (64B data + 32B pad)
#define TILE_BYTES (128 * RSW)         // 12288
#define STAGE_BYTES (2 * TILE_BYTES)   // 24576 (A + B)
#define SMEM_S (2 * STAGE_BYTES)       // 49152 (2 stages)

// tf32 PV smem geometry (R11)
#define LDA 40                         // [row][k] stride (floats)
#define LDBPV 136                      // [k][n] stride (floats)
#define STAGE_PV (128 * LDA + 32 * LDBPV)   // 9472 floats
#define SMEM_PV (2 * STAGE_PV * 4)          // 75776 B

// Scratch (static device memory; allocation-free per harness rules)
__device__ float    g_S[3][BATCH * L * L];          // S fp32 natural; P tf32 k-perm (in-place)
__device__ uint32_t g_Xw[3][BATCH * L * (D / 2)];   // bf16(X*wM) pairs, k-permuted
__device__ uint32_t g_Yc[2][BATCH * L * (D / 2)];   // bf16(Y) pairs, k-permuted (S-GEMM B)
__device__ float    g_YcF[2][BATCH * L * D];        // tf32(Y) fp32 natural (PV B)
__device__ float    g_r[3][2][BATCH * L];
__device__ float    g_m[3][BATCH * L];
__device__ float    g_v[3][BATCH * D];

// ===========================================================================
// helpers
// ===========================================================================
__device__ __forceinline__ uint32_t f2tf(float f) {
    uint32_t r;
    asm("cvt.rna.tf32.f32 %0, %1;" : "=r"(r) : "f"(f));
    return r;
}
__device__ __forceinline__ float4 cvt4(float4 v) {
    v.x = __uint_as_float(f2tf(v.x));
    v.y = __uint_as_float(f2tf(v.y));
    v.z = __uint_as_float(f2tf(v.z));
    v.w = __uint_as_float(f2tf(v.w));
    return v;
}
// float within-8-group k permutation {0,4,1,5,2,6,3,7} via lane-pair shfl (R11)
__device__ __forceinline__ float4 perm8(float4 v) {
    float4 q;
    q.x = __shfl_xor_sync(0xFFFFFFFFu, v.x, 1);
    q.y = __shfl_xor_sync(0xFFFFFFFFu, v.y, 1);
    q.z = __shfl_xor_sync(0xFFFFFFFFu, v.z, 1);
    q.w = __shfl_xor_sync(0xFFFFFFFFu, v.w, 1);
    return (threadIdx.x & 1) ? make_float4(q.z, v.z, q.w, v.w)
                             : make_float4(v.x, q.x, v.y, q.y);
}
__device__ __forceinline__ uint32_t pk(float a, float b) {
    __nv_bfloat162 h = __floats2bfloat162_rn(a, b);   // low = a (even col)
    return *reinterpret_cast<uint32_t*>(&h);
}
// Write 16 cols (v[0..3]) as 8 bf16x2 pairs, order {p0,p4,p1,p5,p2,p6,p3,p7}
__device__ __forceinline__ void store_perm(uint32_t* dst_row, int g, const float4* v) {
    uint4* o = (uint4*)(dst_row + 8 * g);
    o[0] = make_uint4(pk(v[0].x, v[0].y), pk(v[2].x, v[2].y),
                      pk(v[0].z, v[0].w), pk(v[2].z, v[2].w));
    o[1] = make_uint4(pk(v[1].x, v[1].y), pk(v[3].x, v[3].y),
                      pk(v[1].z, v[1].w), pk(v[3].z, v[3].w));
}
__device__ __forceinline__ void mma16(float* c, uint32_t a0, uint32_t a1, uint32_t a2,
                                      uint32_t a3, uint32_t b0, uint32_t b1) {
    asm volatile(
        "mma.sync.aligned.m16n8k16.row.col.f32.bf16.bf16.f32 "
        "{%0,%1,%2,%3}, {%4,%5,%6,%7}, {%8,%9}, {%0,%1,%2,%3};"
        : "+f"(c[0]), "+f"(c[1]), "+f"(c[2]), "+f"(c[3])
        : "r"(a0), "r"(a1), "r"(a2), "r"(a3), "r"(b0), "r"(b1));
}
__device__ __forceinline__ void mma8(float* c, const uint32_t* a, const uint32_t* b) {
    asm volatile(
        "mma.sync.aligned.m16n8k8.row.col.f32.tf32.tf32.f32 "
        "{%0,%1,%2,%3}, {%4,%5,%6,%7}, {%8,%9}, {%0,%1,%2,%3};"
        : "+f"(c[0]), "+f"(c[1]), "+f"(c[2]), "+f"(c[3])
        : "r"(a[0]), "r"(a[1]), "r"(a[2]), "r"(a[3]), "r"(b[0]), "r"(b[1]));
}
__device__ __forceinline__ void cp16(void* dst, const void* src) {
    uint32_t d = (uint32_t)__cvta_generic_to_shared(dst);
    asm volatile("cp.async.cg.shared.global [%0], [%1], 16;" :: "r"(d), "l"(src) : "memory");
}
__device__ __forceinline__ void cp_commit() {
    asm volatile("cp.async.commit_group;" ::: "memory");
}

// ===========================================================================
// prep: per encoder matrix: 2 row-dots + operand copies + enc->out copy
//  d1/d2: bf16 permuted (S-GEMM operands); df: tf32 fp32 natural (PV B)
// grid (512, 3), 256 threads; warp per row; lane g owns cols 16g..16g+15
// ===========================================================================
__global__ void prep_kernel(const float* __restrict__ ea, const float* __restrict__ eb,
                            const float* __restrict__ ec,
                            const float* __restrict__ wab, const float* __restrict__ wac,
                            const float* __restrict__ wbc, float* __restrict__ out) {
    int mat = blockIdx.y;
    int row = blockIdx.x * 8 + (threadIdx.x >> 5);
    int g = threadIdx.x & 31;

    const float *src, *w1, *w2, *sc1, *sc2;
    float *r1, *r2, *df;
    uint32_t *d1, *d2;
    if (mat == 0) {
        src = ea; w1 = wab; r1 = &g_r[0][0][0]; w2 = wac; r2 = &g_r[1][0][0];
        sc1 = wab + 1024; d1 = g_Xw[0];
        sc2 = wac + 1024; d2 = g_Xw[1];
        df = nullptr;
    } else if (mat == 1) {
        src = eb; w1 = wab + 512; r1 = &g_r[0][1][0]; w2 = wbc; r2 = &g_r[2][0][0];
        sc1 = wbc + 1024; d1 = g_Xw[2];
        sc2 = nullptr; d2 = g_Yc[0];
        df = g_YcF[0];
    } else {
        src = ec; w1 = wac + 512; r1 = &g_r[1][1][0]; w2 = wbc + 512; r2 = &g_r[2][1][0];
        sc1 = nullptr; d1 = g_Yc[1];
        sc2 = nullptr; d2 = nullptr;
        df = g_YcF[1];
    }

    const float* rp = src + (size_t)row * D + 16 * g;
    float4 x[4];
    float s1 = 0.f, s2 = 0.f;
#pragma unroll
    for (int t = 0; t < 4; t++) {
        x[t] = *(const float4*)(rp + 4 * t);
        float4 a = *(const float4*)(w1 + 16 * g + 4 * t);
        s1 += x[t].x * a.x + x[t].y * a.y + x[t].z * a.z + x[t].w * a.w;
        float4 b = *(const float4*)(w2 + 16 * g + 4 * t);
        s2 += x[t].x * b.x + x[t].y * b.y + x[t].z * b.z + x[t].w * b.w;
    }
#pragma unroll
    for (int o = 16; o; o >>= 1) {
        s1 += __shfl_xor_sync(0xFFFFFFFFu, s1, o);
        s2 += __shfl_xor_sync(0xFFFFFFFFu, s2, o);
    }
    if (!g) { r1[row] = s1; r2[row] = s2; }

    // encoder raw copy into output section `mat`
    {
        int b = row >> 9, r = row & 511;
        float* orow = out + ((size_t)b * OUTR + mat * 512 + r) * OUTC + 16 * g;
#pragma unroll
        for (int t = 0; t < 4; t++) *(float4*)(orow + 4 * t) = x[t];
    }

    // bf16 operand 1 (scaled if sc1)
    {
        float4 v[4];
#pragma unroll
        for (int t = 0; t < 4; t++) {
            v[t] = x[t];
            if (sc1) {
                float4 s = *(const float4*)(sc1 + 16 * g + 4 * t);
                v[t].x *= s.x; v[t].y *= s.y; v[t].z *= s.z; v[t].w *= s.w;
            }
        }
        store_perm(d1 + (size_t)row * 256, g, v);
    }
    // bf16 operand 2 (scaled if sc2)
    if (d2) {
        float4 v[4];
#pragma unroll
        for (int t = 0; t < 4; t++) {
            v[t] = x[t];
            if (sc2) {
                float4 s = *(const float4*)(sc2 + 16 * g + 4 * t);
                v[t].x *= s.x; v[t].y *= s.y; v[t].z *= s.z; v[t].w *= s.w;
            }
        }
        store_perm(d2 + (size_t)row * 256, g, v);
    }
    // tf32 fp32 natural copy (PV B operand)
    if (df) {
        float* drow = df + (size_t)row * D + 16 * g;
#pragma unroll
        for (int t = 0; t < 4; t++) *(float4*)(drow + 4 * t) = cvt4(x[t]);
    }
}

// ===========================================================================
// S GEMM (per pair, bf16 m16n8k16): S = rX + rY + Xw @ Yc^T.  grid (4,4,8)
// Both operands store_perm bf16 — sigma-robust. 8 warps 2x4, warp tile 64x32.
// ===========================================================================
__global__ __launch_bounds__(256, 2)
void gemm_s_mma(int pair, int yt) {
    extern __shared__ char smc[];
    int b = blockIdx.z;
    int i0 = blockIdx.y * 128, j0 = blockIdx.x * 128;
    const char* Agc = (const char*)g_Xw[pair] + ((size_t)b * L + i0) * 1024;
    const char* Bgc = (const char*)g_Yc[yt] + ((size_t)b * L + j0) * 1024;
    int tid = threadIdx.x;
    int lane = tid & 31, w = tid >> 5;
    int ar = lane >> 2, ac = lane & 3;
    int mbase = (w & 1) * 64, nbase = (w >> 1) * 32;
    float acc[4][4][4] = {};

    auto issue = [&](int c, int st) {
        char* As = smc + st * STAGE_BYTES;
        char* Bs = As + TILE_BYTES;
#pragma unroll
        for (int it = 0; it < 2; it++) {
            int i = it * 256 + tid;
            int row = i >> 2, q = i & 3;
            cp16(As + row * RSW + q * 16, Agc + (size_t)row * 1024 + c * 64 + q * 16);
            cp16(Bs + row * RSW + q * 16, Bgc + (size_t)row * 1024 + c * 64 + q * 16);
        }
        cp_commit();
    };

    issue(0, 0);
    for (int c = 0; c < NCHUNK; c++) {
        asm volatile("cp.async.wait_group 0;" ::: "memory");
        __syncthreads();
        if (c + 1 < NCHUNK) issue(c + 1, (c + 1) & 1);
        const char* a_s = smc + (c & 1) * STAGE_BYTES;
        const char* b_s = a_s + TILE_BYTES;
#pragma unroll
        for (int ks = 0; ks < 2; ks++) {
            uint2 alo[4], ahi[4], bfr[4];
#pragma unroll
            for (int mt = 0; mt < 4; mt++) {
                const char* p = a_s + (mbase + mt * 16 + ar) * RSW + ks * 32 + ac * 8;
                alo[mt] = *(const uint2*)p;
                ahi[mt] = *(const uint2*)(p + 8 * RSW);
            }
#pragma unroll
            for (int nt = 0; nt < 4; nt++)
                bfr[nt] = *(const uint2*)(b_s + (nbase + nt * 8 + ar) * RSW + ks * 32 + ac * 8);
#pragma unroll
            for (int mt = 0; mt < 4; mt++)
#pragma unroll
                for (int nt = 0; nt < 4; nt++)
                    mma16(acc[mt][nt], alo[mt].x, ahi[mt].x, alo[mt].y, ahi[mt].y,
                          bfr[nt].x, bfr[nt].y);
        }
    }

    const float* rx = g_r[pair][0] + b * L + i0;
    const float* ry = g_r[pair][1] + b * L + j0;
    float* Sp = g_S[pair] + ((size_t)b * L + i0) * L + j0;
#pragma unroll
    for (int mt = 0; mt < 4; mt++) {
        int r = mbase + mt * 16 + ar;
        float rx0 = rx[r], rx1 = rx[r + 8];
#pragma unroll
        for (int nt = 0; nt < 4; nt++) {
            int cI = nbase + nt * 8 + ac * 2;
            float ry0 = ry[cI], ry1 = ry[cI + 1];
            float2 v0 = make_float2(acc[mt][nt][0] + rx0 + ry0, acc[mt][nt][1] + rx0 + ry1);
            float2 v1 = make_float2(acc[mt][nt][2] + rx1 + ry0, acc[mt][nt][3] + rx1 + ry1);
            *(float2*)(Sp + (size_t)r * L + cI) = v0;
            *(float2*)(Sp + (size_t)(r + 8) * L + cI) = v1;
        }
    }
}

// ===========================================================================
// softmax (per pair, R11): in-place row softmax; P stored tf32 + float-perm8.
// ===========================================================================
__global__ void softmax_kernel(int pair) {
    int row = blockIdx.x * 8 + (threadIdx.x >> 5);
    int lane = threadIdx.x & 31;
    float* r = g_S[pair] + (size_t)row * L;
    float4 v[4];
    float mx = -1e30f;
#pragma unroll
    for (int t = 0; t < 4; t++) {
        v[t] = ((float4*)r)[t * 32 + lane];
        mx = fmaxf(mx, fmaxf(fmaxf(v[t].x, v[t].y), fmaxf(v[t].z, v[t].w)));
    }
#pragma unroll
    for (int o = 16; o; o >>= 1) mx = fmaxf(mx, __shfl_xor_sync(0xFFFFFFFFu, mx, o));
    float s = 0.f;
#pragma unroll
    for (int t = 0; t < 4; t++) {
        v[t].x = __expf(v[t].x - mx);
        v[t].y = __expf(v[t].y - mx);
        v[t].z = __expf(v[t].z - mx);
        v[t].w = __expf(v[t].w - mx);
        s += v[t].x + v[t].y + v[t].z + v[t].w;
    }
#pragma unroll
    for (int o = 16; o; o >>= 1) s += __shfl_xor_sync(0xFFFFFFFFu, s, o);
    float inv = 1.f / s;
#pragma unroll
    for (int t = 0; t < 4; t++) {
        v[t].x *= inv; v[t].y *= inv; v[t].z *= inv; v[t].w *= inv;
        ((float4*)r)[t * 32 + lane] = perm8(cvt4(v[t]));
    }
    if (!lane) g_m[pair][row] = mx;
}

// ===========================================================================
// PV GEMM (per pair, R11 tf32 m16n8k8): O = P @ Yc; fused concat writes.
// A = g_S (tf32 float-perm), B = g_YcF [k][n] natural.  grid (4,4,8)
// ===========================================================================
__global__ __launch_bounds__(256, 2)
void gemm_pv_mma(int pair, int yt, const float* __restrict__ E, float* __restrict__ out,
                 int secRow, int offRaw, int offProd) {
    extern __shared__ float sm[];
    int b = blockIdx.z;
    int i0 = blockIdx.y * 128, d0 = blockIdx.x * 128;
    const float* Ag = g_S[pair] + ((size_t)b * L + i0) * L;
    const float* Bg = g_YcF[yt] + (size_t)b * L * D + d0;
    int tid = threadIdx.x;

    int lane = tid & 31, w = tid >> 5;
    int ar = lane >> 2, ac = lane & 3;
    int mbase = (w & 1) * 64, nbase = (w >> 1) * 32;
    float acc[4][4][4] = {};

    auto issue = [&](int c, int st) {
        float* As = sm + st * STAGE_PV;
        float* Bs = As + 128 * LDA;
        int k0 = c * 32;
#pragma unroll
        for (int it = 0; it < 4; it++) {
            int i = it * 256 + tid;
            int arow = i >> 3, ac4 = (i & 7) << 2;
            cp16(As + arow * LDA + ac4, Ag + (size_t)arow * L + k0 + ac4);
            int brow = i >> 5, bc4 = (i & 31) << 2;
            cp16(Bs + brow * LDBPV + bc4, Bg + (size_t)(k0 + brow) * D + bc4);
        }
        cp_commit();
    };

    issue(0, 0);
    for (int c = 0; c < NCHUNK; c++) {
        asm volatile("cp.async.wait_group 0;" ::: "memory");
        __syncthreads();
        if (c + 1 < NCHUNK) issue(c + 1, (c + 1) & 1);
        const float* a_s = sm + (c & 1) * STAGE_PV;
        const float* b_s = a_s + 128 * LDA;
#pragma unroll
        for (int ks = 0; ks < 4; ks++) {
            uint32_t af[4][4], bf[4][2];
#pragma unroll
            for (int mt = 0; mt < 4; mt++) {
                const float* p = a_s + (mbase + mt * 16 + ar) * LDA + ks * 8 + ac * 2;
                float2 a0 = *(const float2*)p;
                float2 a1 = *(const float2*)(p + 8 * LDA);
                af[mt][0] = __float_as_uint(a0.x);
                af[mt][1] = __float_as_uint(a1.x);
                af[mt][2] = __float_as_uint(a0.y);
                af[mt][3] = __float_as_uint(a1.y);
            }
#pragma unroll
            for (int nt = 0; nt < 4; nt++) {
                const float* q = b_s + (ks * 8 + ac) * LDBPV + nbase + nt * 8 + ar;
                bf[nt][0] = __float_as_uint(q[0]);
                bf[nt][1] = __float_as_uint(q[4 * LDBPV]);
            }
#pragma unroll
            for (int mt = 0; mt < 4; mt++)
#pragma unroll
                for (int nt = 0; nt < 4; nt++) mma8(acc[mt][nt], af[mt], bf[nt]);
        }
    }

#pragma unroll
    for (int mt = 0; mt < 4; mt++) {
        int r = mbase + mt * 16 + ar;
        int i = i0 + r;
        const float* e0p = E + ((size_t)b * L + i) * D + d0;
        float* o0p = out + ((size_t)b * OUTR + secRow + i) * OUTC;
#pragma unroll
        for (int nt = 0; nt < 4; nt++) {
            int cI = nbase + nt * 8 + ac * 2;
            float2 e0 = *(const float2*)(e0p + cI);
            float2 e1 = *(const float2*)(e0p + 8 * D + cI);
            float2 v0 = make_float2(acc[mt][nt][0], acc[mt][nt][1]);
            float2 v1 = make_float2(acc[mt][nt][2], acc[mt][nt][3]);
            *(float2*)(o0p + offRaw + d0 + cI) = v0;
            *(float2*)(o0p + 8 * OUTC + offRaw + d0 + cI) = v1;
            *(float2*)(o0p + offProd + d0 + cI) = make_float2(v0.x * e0.x, v0.y * e0.y);
            *(float2*)(o0p + 8 * OUTC + offProd + d0 + cI) = make_float2(v1.x * e1.x, v1.y * e1.y);
        }
    }
}

// ===========================================================================
// beta (per pair): beta = softmax_i(m); v = sum_i beta_i * X[b,i,:]. grid (8)
// ===========================================================================
__global__ __launch_bounds__(512)
void beta_b2a_kernel(int pair, const float* __restrict__ X) {
    int b = blockIdx.x, t = threadIdx.x;
    int lane = t & 31, wid = t >> 5;
    __shared__ float sb[512];
    __shared__ float redm[16];
    __shared__ float reds[16];
    __shared__ float bc[2];
    float mv = g_m[pair][b * L + t];
    float v = mv;
#pragma unroll
    for (int o = 16; o; o >>= 1) v = fmaxf(v, __shfl_xor_sync(0xFFFFFFFFu, v, o));
    if (!lane) redm[wid] = v;
    __syncthreads();
    if (t == 0) {
        float m2 = redm[0];
        for (int i = 1; i < 16; i++) m2 = fmaxf(m2, redm[i]);
        bc[0] = m2;
    }
    __syncthreads();
    float mx = bc[0];
    float e = __expf(mv - mx);
    v = e;
#pragma unroll
    for (int o = 16; o; o >>= 1) v += __shfl_xor_sync(0xFFFFFFFFu, v, o);
    if (!lane) reds[wid] = v;
    __syncthreads();
    if (t == 0) {
        float s = 0.f;
        for (int i = 0; i < 16; i++) s += reds[i];
        bc[1] = s;
    }
    __syncthreads();
    sb[t] = e / bc[1];
    __syncthreads();
    const float* Xb = X + (size_t)b * L * D;
    float acc = 0.f;
#pragma unroll 8
    for (int i = 0; i < L; i++) acc += sb[i] * Xb[(size_t)i * D + t];
    g_v[pair][b * D + t] = acc;
}

// ===========================================================================
// bcast (per pair): vec + E*vec into Y-side section. grid (512, 8)
// ===========================================================================
__global__ void bcast_kernel(int pair, const float* __restrict__ E, float* __restrict__ out,
                             int secRow, int offRaw, int offProd) {
    int b = blockIdx.y, r = blockIdx.x;
    int t = threadIdx.x;
    float4 vv = ((const float4*)(&g_v[pair][b * D]))[t];
    float4 ee = ((const float4*)(E + ((size_t)b * L + r) * D))[t];
    float* row = out + ((size_t)b * OUTR + secRow + r) * OUTC;
    ((float4*)(row + offRaw))[t] = vv;
    float4 p = make_float4(vv.x * ee.x, vv.y * ee.y, vv.z * ee.z, vv.w * ee.w);
    ((float4*)(row + offProd))[t] = p;
}

// ===========================================================================
extern "C" void kernel_launch(void* const* d_in, const int* in_sizes, int n_in,
                              void* d_out, int out_size) {
    const float* ea = (const float*)d_in[0];
    const float* eb = (const float*)d_in[1];
    const float* ec = (const float*)d_in[2];
    const float* wab = (const float*)d_in[3];
    const float* wac = (const float*)d_in[4];
    const float* wbc = (const float*)d_in[5];
    float* out = (float*)d_out;

    static cudaStream_t st[3];
    static cudaEvent_t evPrep, evDone[3];
    static bool inited = false;
    if (!inited) {
        for (int i = 0; i < 3; i++) cudaStreamCreateWithFlags(&st[i], cudaStreamNonBlocking);
        cudaEventCreateWithFlags(&evPrep, cudaEventDisableTiming);
        for (int i = 0; i < 3; i++) cudaEventCreateWithFlags(&evDone[i], cudaEventDisableTiming);
        cudaFuncSetAttribute(gemm_s_mma, cudaFuncAttributeMaxDynamicSharedMemorySize, SMEM_S);
        cudaFuncSetAttribute(gemm_pv_mma, cudaFuncAttributeMaxDynamicSharedMemorySize, SMEM_PV);
        inited = true;
    }

    struct PairCfg {
        const float *X, *Y; int yt;
        int secRowA, offRawA, offProdA;
        int secRowV, offRawV, offProdV;
    };
    const PairCfg cfg[3] = {
        {ea, eb, 0,   0,  512, 1536,   512,  512, 1536},  // ab
        {ea, ec, 1,   0, 1024, 2048,  1024,  512, 1536},  // ac
        {eb, ec, 1, 512, 1024, 2048,  1024, 1024, 2048},  // bc
    };

    prep_kernel<<<dim3(512, 3), 256>>>(ea, eb, ec, wab, wac, wbc, out);
    cudaEventRecord(evPrep, 0);

    for (int p = 0; p < 3; p++) {
        cudaStreamWaitEvent(st[p], evPrep, 0);
        gemm_s_mma<<<dim3(4, 4, 8), 256, SMEM_S, st[p]>>>(p, cfg[p].yt);
        softmax_kernel<<<512, 256, 0, st[p]>>>(p);
        gemm_pv_mma<<<dim3(4, 4, 8), 256, SMEM_PV, st[p]>>>(
            p, cfg[p].yt, cfg[p].X, out, cfg[p].secRowA, cfg[p].offRawA, cfg[p].offProdA);
        beta_b2a_kernel<<<8, 512, 0, st[p]>>>(p, cfg[p].X);
        bcast_kernel<<<dim3(512, 8), 128, 0, st[p]>>>(
            p, cfg[p].Y, out, cfg[p].secRowV, cfg[p].offRawV, cfg[p].offProdV);
        cudaEventRecord(evDone[p], st[p]);
    }
    for (int p = 0; p < 3; p++) cudaStreamWaitEvent(0, evDone[p], 0);
}